// round 5
// baseline (speedup 1.0000x reference)
#include <cuda_runtime.h>
#include <cstdint>

// Problem shape (fixed by the dataset)
#define BB 8
#define SS 128
#define RR 192
#define CC 192
#define NX (CC / 4)   // 48 float4 segments per row

#define RTILES (RR / 4)                // 48
#define STILES (SS / 2)                // 64
#define NTILES (BB * STILES * RTILES)  // 24576
#define NBLOCKS 888                    // 148 SMs * 6 resident CTAs

// SPACING = (2.0, 1.5, 1.5) along (S, R, C)
#define INV2DX 0.25f
#define INV2DY 0.33333333333333333f
#define INV2DZ 0.33333333333333333f
#define INVDX2 0.25f
#define INVDY2 0.44444444444444444f
#define INVDZ2 0.44444444444444444f
// K = -2 * (INVDX2 + INVDY2 + INVDZ2)
#define KNEG_C (-2.2777777777777777f)

typedef unsigned long long ull;

__device__ __forceinline__ int clamp_i(int v, int lo, int hi) {
    return min(max(v, lo), hi);
}

// ---- packed f32x2 helpers (SASS FFMA2/FADD2/FMUL2 — PTX-only path) ----
__device__ __forceinline__ ull f2fma(ull a, ull b, ull c) {
    ull r; asm("fma.rn.f32x2 %0, %1, %2, %3;" : "=l"(r) : "l"(a), "l"(b), "l"(c)); return r;
}
__device__ __forceinline__ ull f2mul(ull a, ull b) {
    ull r; asm("mul.rn.f32x2 %0, %1, %2;" : "=l"(r) : "l"(a), "l"(b)); return r;
}
__device__ __forceinline__ ull f2add(ull a, ull b) {
    ull r; asm("add.rn.f32x2 %0, %1, %2;" : "=l"(r) : "l"(a), "l"(b)); return r;
}
__device__ __forceinline__ ull pk2(float a, float b) {
    return (ull)__float_as_uint(a) | ((ull)__float_as_uint(b) << 32);
}
__device__ __forceinline__ float lo32(ull v) { return __uint_as_float((unsigned)v); }
__device__ __forceinline__ float hi32(ull v) { return __uint_as_float((unsigned)(v >> 32)); }

struct PkC {   // hoisted packed constants
    ull NEG1, C2DX, C2DY, C2DZ, CDX2, CDY2, CDZ2, KNEG, HALF;
};

// One output float4 for one plane, packed math.
__device__ __forceinline__ float4 plane_out(const float4 c,
                                            const float4 xm, const float4 xp,
                                            const float4 ym, const float4 yp,
                                            const float left, const float right,
                                            const float4 d,
                                            const bool lo, const bool hi,
                                            const PkC& K)
{
    const ull c01  = pk2(c.x,  c.y),  c23  = pk2(c.z,  c.w);
    const ull xm01 = pk2(xm.x, xm.y), xm23 = pk2(xm.z, xm.w);
    const ull xp01 = pk2(xp.x, xp.y), xp23 = pk2(xp.z, xp.w);
    const ull ym01 = pk2(ym.x, ym.y), ym23 = pk2(ym.z, ym.w);
    const ull yp01 = pk2(yp.x, yp.y), yp23 = pk2(yp.z, yp.w);
    const ull zm01 = pk2(left, c.x),  zm23 = pk2(c.y,  c.z);
    const ull zp01 = pk2(c.y,  c.z),  zp23 = pk2(c.w,  right);
    const ull d01  = pk2(d.x,  d.y),  d23  = pk2(d.z,  d.w);

    // F = (dx*inv2dx)^2 + (dy*inv2dy)^2 + (dz*inv2dz)^2
    ull t, F01, F23;
    t = f2mul(f2fma(xm01, K.NEG1, xp01), K.C2DX); F01 = f2mul(t, t);
    t = f2mul(f2fma(ym01, K.NEG1, yp01), K.C2DY); F01 = f2fma(t, t, F01);
    t = f2mul(f2fma(zm01, K.NEG1, zp01), K.C2DZ); F01 = f2fma(t, t, F01);
    t = f2mul(f2fma(xm23, K.NEG1, xp23), K.C2DX); F23 = f2mul(t, t);
    t = f2mul(f2fma(ym23, K.NEG1, yp23), K.C2DY); F23 = f2fma(t, t, F23);
    t = f2mul(f2fma(zm23, K.NEG1, zp23), K.C2DZ); F23 = f2fma(t, t, F23);

    // G = (xp+xm)*cdx2 + (yp+ym)*cdy2 + (zp+zm)*cdz2 + K*c
    ull G01 = f2mul(c01, K.KNEG);
    G01 = f2fma(f2add(xp01, xm01), K.CDX2, G01);
    G01 = f2fma(f2add(yp01, ym01), K.CDY2, G01);
    G01 = f2fma(f2add(zp01, zm01), K.CDZ2, G01);
    ull G23 = f2mul(c23, K.KNEG);
    G23 = f2fma(f2add(xp23, xm23), K.CDX2, G23);
    G23 = f2fma(f2add(yp23, ym23), K.CDY2, G23);
    G23 = f2fma(f2add(zp23, zm23), K.CDZ2, G23);

    // o = -(0.5*F + d*G)  (sign flip via xor on both packed halves)
    ull o01 = f2fma(F01, K.HALF, f2mul(d01, G01)) ^ 0x8000000080000000ULL;
    ull o23 = f2fma(F23, K.HALF, f2mul(d23, G23)) ^ 0x8000000080000000ULL;

    float4 o = make_float4(lo32(o01), hi32(o01), lo32(o23), hi32(o23));

    if (lo) {
        // scalar xy-partials at comp 1 (column k=1)
        const float gx1 = (xp.y - xm.y) * INV2DX;
        const float gy1 = (yp.y - ym.y) * INV2DY;
        const float Fxy1 = gx1 * gx1 + gy1 * gy1;
        const float Gxy1 = (xp.y - 2.0f * c.y + xm.y) * INVDX2
                         + (yp.y - 2.0f * c.y + ym.y) * INVDY2;
        // k=1: zm tap is Q(0)=P[col 1]=c.y
        const float gz1 = (c.z - c.y) * INV2DZ;
        const float Gz1 = (c.z - c.y) * INVDZ2;
        o.y = -0.5f * (Fxy1 + gz1 * gz1) - d.y * (Gxy1 + Gz1);
        // k=0: all column taps clamp to col 1; gz=0, Gz=0
        o.x = -0.5f * Fxy1 - d.x * Gxy1;
    }
    if (hi) {
        // scalar xy-partials at comp 2 (column k=190)
        const float gx2 = (xp.z - xm.z) * INV2DX;
        const float gy2 = (yp.z - ym.z) * INV2DY;
        const float Fxy2 = gx2 * gx2 + gy2 * gy2;
        const float Gxy2 = (xp.z - 2.0f * c.z + xm.z) * INVDX2
                         + (yp.z - 2.0f * c.z + ym.z) * INVDY2;
        // k=190: zp tap is Q(191)=P[col 190]=c.z
        const float gz2 = (c.z - c.y) * INV2DZ;
        const float Gz2 = (c.y - c.z) * INVDZ2;
        o.z = -0.5f * (Fxy2 + gz2 * gz2) - d.z * (Gxy2 + Gz2);
        // k=191: all column taps clamp to col 190; gz=0, Gz=0
        o.w = -0.5f * Fxy2 - d.w * Gxy2;
    }

    return o;
}

__global__ __launch_bounds__(192, 6)
void flowp_kernel_pk(const float* __restrict__ P,
                     const float* __restrict__ D,
                     float* __restrict__ out)
{
    const int tx = threadIdx.x;          // 0..47 : float4 index along C
    const int ty = threadIdx.y;          // 0..3  : r within tile
    const int k0 = tx * 4;
    const bool lo = (tx == 0);
    const bool hi = (tx == NX - 1);

    const int kl = lo ? k0 : k0 - 1;
    const int kr = hi ? CC - 1 : k0 + 4;

    PkC K;
    K.NEG1 = pk2(-1.0f, -1.0f);
    K.C2DX = pk2(INV2DX, INV2DX);
    K.C2DY = pk2(INV2DY, INV2DY);
    K.C2DZ = pk2(INV2DZ, INV2DZ);
    K.CDX2 = pk2(INVDX2, INVDX2);
    K.CDY2 = pk2(INVDY2, INVDY2);
    K.CDZ2 = pk2(INVDZ2, INVDZ2);
    K.KNEG = pk2(KNEG_C, KNEG_C);
    K.HALF = pk2(0.5f, 0.5f);

    for (int T = blockIdx.x; T < NTILES; T += NBLOCKS) {
        const int rb   = T % RTILES;
        const int rest = T / RTILES;
        const int st   = rest & (STILES - 1);
        const int b    = rest >> 6;          // / STILES (=64)

        const int r  = rb * 4 + ty;
        const int s0 = st * 2;

        const int i0 = clamp_i(s0 - 1, 1, SS - 2);
        const int i1 = clamp_i(s0,     1, SS - 2);
        const int i2 = clamp_i(s0 + 1, 1, SS - 2);
        const int i3 = clamp_i(s0 + 2, 1, SS - 2);

        const int cr = clamp_i(r,     1, RR - 2);
        const int rm = clamp_i(r - 1, 1, RR - 2);
        const int rp = clamp_i(r + 1, 1, RR - 2);

        const long long base = (long long)b * (SS * RR * CC);
        const float* Pb = P + base;

        const int rowA   = (i0 * RR + cr) * CC;
        const int rowC1  = (i1 * RR + cr) * CC;
        const int rowC2  = (i2 * RR + cr) * CC;
        const int rowBp  = (i3 * RR + cr) * CC;
        const int rowY1m = (i1 * RR + rm) * CC;
        const int rowY1p = (i1 * RR + rp) * CC;
        const int rowY2m = (i2 * RR + rm) * CC;
        const int rowY2p = (i2 * RR + rp) * CC;

        const float4 A   = __ldg((const float4*)(Pb + rowA   + k0));
        const float4 C1  = __ldg((const float4*)(Pb + rowC1  + k0));
        const float4 C2  = __ldg((const float4*)(Pb + rowC2  + k0));
        const float4 Bp  = __ldg((const float4*)(Pb + rowBp  + k0));
        const float4 Y1m = __ldg((const float4*)(Pb + rowY1m + k0));
        const float4 Y1p = __ldg((const float4*)(Pb + rowY1p + k0));
        const float4 Y2m = __ldg((const float4*)(Pb + rowY2m + k0));
        const float4 Y2p = __ldg((const float4*)(Pb + rowY2p + k0));

        const float l1 = __ldg(Pb + rowC1 + kl);
        const float r1 = __ldg(Pb + rowC1 + kr);
        const float l2 = __ldg(Pb + rowC2 + kl);
        const float r2 = __ldg(Pb + rowC2 + kr);

        const long long idx0 = base + ((long long)(s0 * RR + r)) * CC + k0;
        const long long idx1 = idx0 + (long long)RR * CC;
        const float4 d0 = __ldg((const float4*)(D + idx0));
        const float4 d1 = __ldg((const float4*)(D + idx1));

        const float4 o0 = plane_out(C1, A,  C2, Y1m, Y1p, l1, r1, d0, lo, hi, K);
        const float4 o1 = plane_out(C2, C1, Bp, Y2m, Y2p, l2, r2, d1, lo, hi, K);

        *((float4*)(out + idx0)) = o0;
        *((float4*)(out + idx1)) = o1;
    }
}

extern "C" void kernel_launch(void* const* d_in, const int* in_sizes, int n_in,
                              void* d_out, int out_size)
{
    // inputs (metadata order): t (unused), batch_P, D
    const float* P = (const float*)d_in[1];
    const float* D = (const float*)d_in[2];
    float* out = (float*)d_out;

    dim3 grid(NBLOCKS);
    dim3 block(NX, 4);   // 192 threads
    flowp_kernel_pk<<<grid, block>>>(P, D, out);
}